// round 3
// baseline (speedup 1.0000x reference)
#include <cuda_runtime.h>
#include <math.h>
#include <stdint.h>

#define T_STEPS 2048
#define BATCH   32
#define HID     256
#define ZCOLS   1024            // 4*HID, gate order f,i,o,c
#define NCTA    128             // recurrence CTAs (all co-resident)
#define UNITS_PER_CTA 2
#define REC_THREADS 256

// ---------------- scratch (device globals: no allocations allowed) ----------
__device__ float g_Zx[(size_t)T_STEPS * BATCH * ZCOLS];   // 256 MB: x@Wx4 + b4
__device__ float g_h[2][HID * BATCH];                     // ping-pong h, [unit][b]
__device__ int   g_bar_count;                             // monotone arrival counter
__device__ int   g_flag[NCTA * 32];                       // per-CTA release flag, 128B apart

// ============================================================================
// Kernel 1: Zx[t*32+b][g*256+j] = sum_k x[b][t][k] * Wg[k][j] + bg[j]
// 128x128 tile SGEMM, BK=16, 256 threads, 8x8 microtile.
// ============================================================================
__global__ __launch_bounds__(256, 2)
void gemm_zx(const float* __restrict__ x,
             const float* __restrict__ Wf, const float* __restrict__ bf,
             const float* __restrict__ Wi, const float* __restrict__ bi,
             const float* __restrict__ Wo, const float* __restrict__ bo,
             const float* __restrict__ Wc, const float* __restrict__ bc)
{
    __shared__ float As[16 * 128];   // [k][m]
    __shared__ float Bs[16 * 128];   // [k][n]

    const int t = threadIdx.x;

    // reset recurrence sync state (runs sometime during this kernel; lstm_rec
    // is stream-ordered after us, so this is replay-safe)
    if (blockIdx.x == 0 && blockIdx.y == 0) {
        if (t == 0) g_bar_count = 0;
        if (t < NCTA) g_flag[t * 32] = 0;
    }

    const float* Wg[4] = {Wf, Wi, Wo, Wc};
    const float* bg[4] = {bf, bi, bo, bc};

    const int N0 = blockIdx.x * 128;          // never straddles a gate
    const int gate = N0 >> 8;
    const int jb = N0 & 255;
    const float* __restrict__ W = Wg[gate];

    const int M0 = blockIdx.y * 128;
    const int tx = t & 15;
    const int ty = t >> 4;

    float acc[8][8];
    #pragma unroll
    for (int i = 0; i < 8; i++)
        #pragma unroll
        for (int j = 0; j < 8; j++) acc[i][j] = 0.f;

    for (int k0 = 0; k0 < 256; k0 += 16) {
        #pragma unroll
        for (int i = 0; i < 2; i++) {
            int f = t + i * 256;
            int kq  = f >> 7;
            int row = f & 127;
            int m   = M0 + row;
            int bb  = m & 31;
            int tt  = m >> 5;
            float4 a = *reinterpret_cast<const float4*>(
                x + ((size_t)bb * T_STEPS + tt) * 256 + k0 + kq * 4);
            As[(kq * 4 + 0) * 128 + row] = a.x;
            As[(kq * 4 + 1) * 128 + row] = a.y;
            As[(kq * 4 + 2) * 128 + row] = a.z;
            As[(kq * 4 + 3) * 128 + row] = a.w;
            int kk = f >> 5;
            int nq = f & 31;
            *reinterpret_cast<float4*>(&Bs[kk * 128 + nq * 4]) =
                *reinterpret_cast<const float4*>(W + (size_t)(k0 + kk) * 256 + jb + nq * 4);
        }
        __syncthreads();

        #pragma unroll
        for (int k = 0; k < 16; k++) {
            float a[8], bv[8];
            *reinterpret_cast<float4*>(&a[0])  = *reinterpret_cast<float4*>(&As[k * 128 + ty * 8]);
            *reinterpret_cast<float4*>(&a[4])  = *reinterpret_cast<float4*>(&As[k * 128 + ty * 8 + 4]);
            *reinterpret_cast<float4*>(&bv[0]) = *reinterpret_cast<float4*>(&Bs[k * 128 + tx * 8]);
            *reinterpret_cast<float4*>(&bv[4]) = *reinterpret_cast<float4*>(&Bs[k * 128 + tx * 8 + 4]);
            #pragma unroll
            for (int i = 0; i < 8; i++)
                #pragma unroll
                for (int j = 0; j < 8; j++)
                    acc[i][j] = fmaf(a[i], bv[j], acc[i][j]);
        }
        __syncthreads();
    }

    const float* __restrict__ bias = bg[gate];
    #pragma unroll
    for (int i = 0; i < 8; i++) {
        int m = M0 + ty * 8 + i;
        float* zr = g_Zx + (size_t)m * ZCOLS + N0 + tx * 8;
        float4 v0, v1;
        v0.x = acc[i][0] + bias[jb + tx * 8 + 0];
        v0.y = acc[i][1] + bias[jb + tx * 8 + 1];
        v0.z = acc[i][2] + bias[jb + tx * 8 + 2];
        v0.w = acc[i][3] + bias[jb + tx * 8 + 3];
        v1.x = acc[i][4] + bias[jb + tx * 8 + 4];
        v1.y = acc[i][5] + bias[jb + tx * 8 + 5];
        v1.z = acc[i][6] + bias[jb + tx * 8 + 6];
        v1.w = acc[i][7] + bias[jb + tx * 8 + 7];
        *reinterpret_cast<float4*>(zr)     = v0;
        *reinterpret_cast<float4*>(zr + 4) = v1;
    }
}

// ============================================================================
// Kernel 2: persistent recurrence, 128 CTAs x 256 threads.
// Grid sync: counter arrival + last-arriver broadcasts per-CTA flags
// (one 128B line per CTA -> contention-free polling).
// ============================================================================
#define WPAD 260   // s_Wh row pitch
#define PPAD 33    // s_part row pitch

// warp0-only: arrive at round `round`; if last, write all per-CTA flags.
__device__ __forceinline__ void arrive_round(int round)
{
    int is_last = 0;
    if (threadIdx.x == 0) {
        int old;
        asm volatile("atom.acq_rel.gpu.global.add.s32 %0, [%1], %2;"
                     : "=r"(old) : "l"(&g_bar_count), "r"(1) : "memory");
        is_last = (old == round * NCTA - 1);
    }
    is_last = __shfl_sync(0xffffffffu, is_last, 0);
    if (is_last) {
        int lane = threadIdx.x;           // 0..31
        #pragma unroll
        for (int j = 0; j < 4; j++) {
            asm volatile("st.release.gpu.global.s32 [%0], %1;"
                         :: "l"(&g_flag[(lane * 4 + j) * 32]), "r"(round) : "memory");
        }
    }
}

__device__ __forceinline__ void wait_round(const int* my_flag, int round)
{
    int v;
    do {
        asm volatile("ld.acquire.gpu.global.s32 %0, [%1];"
                     : "=r"(v) : "l"(my_flag) : "memory");
    } while (v < round);
}

__global__ __launch_bounds__(REC_THREADS, 1)
void lstm_rec(const float* __restrict__ Wf, const float* __restrict__ Wi,
              const float* __restrict__ Wo, const float* __restrict__ Wc,
              float* __restrict__ out)
{
    __shared__ float s_Wh[8 * WPAD];     // [c][k], c = 2*gate + u
    __shared__ float s_h[256 * 32];      // [k][b]
    __shared__ float s_part[32 * PPAD];  // [kq*8+c][b]
    __shared__ float s_c[2 * 32];        // cell state [u][b]

    const int tid = threadIdx.x;
    const int c0  = blockIdx.x * UNITS_PER_CTA;
    const int* my_flag = &g_flag[blockIdx.x * 32];
    const float* Wg[4] = {Wf, Wi, Wo, Wc};

    // stage Wh slice once: s_Wh[c][k] = Wg[c/2][(256+k)*256 + c0 + (c&1)]
    for (int idx = tid; idx < 8 * 256; idx += REC_THREADS) {
        int c = idx >> 8;
        int k = idx & 255;
        s_Wh[c * WPAD + k] = Wg[c >> 1][(size_t)(256 + k) * 256 + c0 + (c & 1)];
    }
    if (tid < 64) s_c[tid] = 0.f;
    if (tid < UNITS_PER_CTA * BATCH) {
        int u = tid >> 5, b = tid & 31;
        g_h[0][(c0 + u) * 32 + b] = 0.f;
    }

    // thread role: kq = k-range (64 k's), c = local z-col (0..7), bq = batch quad
    const int kq = tid >> 6;
    const int r  = tid & 63;
    const int c  = r >> 3;
    const int bq = r & 7;
    const int colg = (c >> 1) * HID + c0 + (c & 1);   // global z column

    const float* wrow = s_Wh + c * WPAD + kq * 64;
    const float* hcol = s_h + (kq * 64) * 32 + 4 * bq;
    float* prow = s_part + (kq * 8 + c) * PPAD + 4 * bq;

    // prefetch Zx(0) (gemm_zx is stream-ordered before us, data is ready)
    float p0 = 0.f, p1 = 0.f, p2 = 0.f, p3 = 0.f;
    if (kq == 0) {
        const float* z = g_Zx + ((size_t)0 * BATCH + 4 * bq) * ZCOLS + colg;
        p0 = __ldcg(z);
        p1 = __ldcg(z + ZCOLS);
        p2 = __ldcg(z + 2 * ZCOLS);
        p3 = __ldcg(z + 3 * ZCOLS);
    }

    // initial grid sync: round 1 (weights staged + h0 zeroed everywhere)
    __syncthreads();
    if (tid < 32) arrive_round(1);
    wait_round(my_flag, 1);

    for (int t = 0; t < T_STEPS; t++) {
        // broadcast h(t) into smem (L1 not coherent across SMs -> __ldcg)
        {
            const float4* hb4 = reinterpret_cast<const float4*>(g_h[t & 1]);
            float4* hs4 = reinterpret_cast<float4*>(s_h);
            #pragma unroll
            for (int i = 0; i < 8; i++)
                hs4[i * 256 + tid] = __ldcg(hb4 + i * 256 + tid);
        }

        // consume prefetched Zx(t); prefetch Zx(t+1) (overlaps FMA below)
        float a0 = p0, a1 = p1, a2 = p2, a3 = p3;
        if (kq == 0 && t + 1 < T_STEPS) {
            const float* z = g_Zx + ((size_t)(t + 1) * BATCH + 4 * bq) * ZCOLS + colg;
            p0 = __ldcg(z);
            p1 = __ldcg(z + ZCOLS);
            p2 = __ldcg(z + 2 * ZCOLS);
            p3 = __ldcg(z + 3 * ZCOLS);
        }
        __syncthreads();          // s_h fully staged

        // partial dot over this thread's 64-k range, 4 batches at once
        #pragma unroll
        for (int k4 = 0; k4 < 16; k4++) {
            float4 w = *reinterpret_cast<const float4*>(wrow + k4 * 4);
            float4 h0 = *reinterpret_cast<const float4*>(hcol + (k4 * 4 + 0) * 32);
            a0 = fmaf(w.x, h0.x, a0); a1 = fmaf(w.x, h0.y, a1);
            a2 = fmaf(w.x, h0.z, a2); a3 = fmaf(w.x, h0.w, a3);
            float4 h1 = *reinterpret_cast<const float4*>(hcol + (k4 * 4 + 1) * 32);
            a0 = fmaf(w.y, h1.x, a0); a1 = fmaf(w.y, h1.y, a1);
            a2 = fmaf(w.y, h1.z, a2); a3 = fmaf(w.y, h1.w, a3);
            float4 h2 = *reinterpret_cast<const float4*>(hcol + (k4 * 4 + 2) * 32);
            a0 = fmaf(w.z, h2.x, a0); a1 = fmaf(w.z, h2.y, a1);
            a2 = fmaf(w.z, h2.z, a2); a3 = fmaf(w.z, h2.w, a3);
            float4 h3 = *reinterpret_cast<const float4*>(hcol + (k4 * 4 + 3) * 32);
            a0 = fmaf(w.w, h3.x, a0); a1 = fmaf(w.w, h3.y, a1);
            a2 = fmaf(w.w, h3.z, a2); a3 = fmaf(w.w, h3.w, a3);
        }
        prow[0] = a0; prow[1] = a1; prow[2] = a2; prow[3] = a3;
        __syncthreads();          // s_part complete

        const int round = t + 2;
        // gates + state update + writeback: warps 0-1, threads (u, b)
        if (tid < 64) {
            int u  = tid >> 5;
            int bb = tid & 31;
            float zf = 0.f, zi = 0.f, zo = 0.f, zg = 0.f;
            #pragma unroll
            for (int q = 0; q < 4; q++) {
                zf += s_part[(q * 8 + 0 + u) * PPAD + bb];
                zi += s_part[(q * 8 + 2 + u) * PPAD + bb];
                zo += s_part[(q * 8 + 4 + u) * PPAD + bb];
                zg += s_part[(q * 8 + 6 + u) * PPAD + bb];
            }
            float fg = 1.f / (1.f + __expf(-zf));
            float ig = 1.f / (1.f + __expf(-zi));
            float og = 1.f / (1.f + __expf(-zo));
            float gg = tanhf(zg);
            float cv = fg * s_c[u * 32 + bb] + ig * gg;
            s_c[u * 32 + bb] = cv;
            float hv = og * tanhf(cv);
            g_h[(t + 1) & 1][(c0 + u) * 32 + bb] = hv;
            // reverse time order: out[b][T-1-t][j]
            out[((size_t)bb * T_STEPS + (T_STEPS - 1 - t)) * HID + c0 + u] = hv;

            if (t + 1 < T_STEPS) {
                asm volatile("bar.sync 1, 64;" ::: "memory");  // warps 0-1 only
                if (tid < 32) arrive_round(round);
            }
        }
        // dot warps go straight to polling; safe: flag(round) implies every
        // CTA passed its s_part syncthreads, so all s_h/s_part readers of
        // step t are done before anyone writes step t+1 data.
        if (t + 1 < T_STEPS) wait_round(my_flag, round);
    }
}

// ============================================================================
extern "C" void kernel_launch(void* const* d_in, const int* in_sizes, int n_in,
                              void* d_out, int out_size)
{
    const float* x  = (const float*)d_in[0];
    const float* Wf = (const float*)d_in[1];
    const float* bf = (const float*)d_in[2];
    const float* Wi = (const float*)d_in[3];
    const float* bi = (const float*)d_in[4];
    const float* Wo = (const float*)d_in[5];
    const float* bo = (const float*)d_in[6];
    const float* Wc = (const float*)d_in[7];
    const float* bc = (const float*)d_in[8];
    float* out = (float*)d_out;

    dim3 g1(ZCOLS / 128, (T_STEPS * BATCH) / 128);   // 8 x 512
    gemm_zx<<<g1, 256>>>(x, Wf, bf, Wi, bi, Wo, bo, Wc, bc);
    lstm_rec<<<NCTA, REC_THREADS>>>(Wf, Wi, Wo, Wc, out);
}

// round 4
// speedup vs baseline: 1.8567x; 1.8567x over previous
#include <cuda_runtime.h>
#include <math.h>
#include <stdint.h>

#define T_STEPS 2048
#define BATCH   32
#define HID     256
#define ZCOLS   1024            // 4*HID, gate order f,i,o,c
#define MROWS   (T_STEPS * BATCH)
#define NCTA    128
#define UNITS_PER_CTA 2
#define REC_THREADS 256

// ---------------- scratch (device globals: no allocations allowed) ----------
// Zx transposed: g_Zx[col][t*32 + b], col-major for coalesced recurrence loads
__device__ float g_Zx[(size_t)ZCOLS * MROWS];             // 256 MB
__device__ float g_h[2][HID * BATCH];                     // ping-pong h, [unit][b]
__device__ int   g_bar_count;                             // monotone arrival counter

// ============================================================================
// Kernel 1: Zx[col][t*32+b] = sum_k x[b][t][k] * Wg[k][j] + bg[j]
// 128x128 tile SGEMM, BK=16, 256 threads, 8x8 microtile. Transposed epilogue.
// ============================================================================
__global__ __launch_bounds__(256, 2)
void gemm_zx(const float* __restrict__ x,
             const float* __restrict__ Wf, const float* __restrict__ bf,
             const float* __restrict__ Wi, const float* __restrict__ bi,
             const float* __restrict__ Wo, const float* __restrict__ bo,
             const float* __restrict__ Wc, const float* __restrict__ bc)
{
    __shared__ float As[16 * 128];   // [k][m]
    __shared__ float Bs[16 * 128];   // [k][n]

    const int t = threadIdx.x;

    // reset recurrence barrier counter (lstm_rec is stream-ordered after us)
    if (blockIdx.x == 0 && blockIdx.y == 0 && t == 0) g_bar_count = 0;

    const float* Wg[4] = {Wf, Wi, Wo, Wc};
    const float* bg[4] = {bf, bi, bo, bc};

    const int N0 = blockIdx.x * 128;          // never straddles a gate
    const int gate = N0 >> 8;
    const int jb = N0 & 255;
    const float* __restrict__ W = Wg[gate];

    const int M0 = blockIdx.y * 128;
    const int tx = t & 15;
    const int ty = t >> 4;

    float acc[8][8];
    #pragma unroll
    for (int i = 0; i < 8; i++)
        #pragma unroll
        for (int j = 0; j < 8; j++) acc[i][j] = 0.f;

    for (int k0 = 0; k0 < 256; k0 += 16) {
        #pragma unroll
        for (int i = 0; i < 2; i++) {
            int f = t + i * 256;
            int kq  = f >> 7;
            int row = f & 127;
            int m   = M0 + row;
            int bb  = m & 31;
            int tt  = m >> 5;
            float4 a = *reinterpret_cast<const float4*>(
                x + ((size_t)bb * T_STEPS + tt) * 256 + k0 + kq * 4);
            As[(kq * 4 + 0) * 128 + row] = a.x;
            As[(kq * 4 + 1) * 128 + row] = a.y;
            As[(kq * 4 + 2) * 128 + row] = a.z;
            As[(kq * 4 + 3) * 128 + row] = a.w;
            int kk = f >> 5;
            int nq = f & 31;
            *reinterpret_cast<float4*>(&Bs[kk * 128 + nq * 4]) =
                *reinterpret_cast<const float4*>(W + (size_t)(k0 + kk) * 256 + jb + nq * 4);
        }
        __syncthreads();

        #pragma unroll
        for (int k = 0; k < 16; k++) {
            float a[8], bv[8];
            *reinterpret_cast<float4*>(&a[0])  = *reinterpret_cast<float4*>(&As[k * 128 + ty * 8]);
            *reinterpret_cast<float4*>(&a[4])  = *reinterpret_cast<float4*>(&As[k * 128 + ty * 8 + 4]);
            *reinterpret_cast<float4*>(&bv[0]) = *reinterpret_cast<float4*>(&Bs[k * 128 + tx * 8]);
            *reinterpret_cast<float4*>(&bv[4]) = *reinterpret_cast<float4*>(&Bs[k * 128 + tx * 8 + 4]);
            #pragma unroll
            for (int i = 0; i < 8; i++)
                #pragma unroll
                for (int j = 0; j < 8; j++)
                    acc[i][j] = fmaf(a[i], bv[j], acc[i][j]);
        }
        __syncthreads();
    }

    // transposed epilogue: store Zx[col][m], m = M0+ty*8+i runs with i
    const float* __restrict__ bias = bg[gate];
    #pragma unroll
    for (int j = 0; j < 8; j++) {
        int col = N0 + tx * 8 + j;
        float bj = bias[jb + tx * 8 + j];
        float4 lo, hi;
        lo.x = acc[0][j] + bj; lo.y = acc[1][j] + bj;
        lo.z = acc[2][j] + bj; lo.w = acc[3][j] + bj;
        hi.x = acc[4][j] + bj; hi.y = acc[5][j] + bj;
        hi.z = acc[6][j] + bj; hi.w = acc[7][j] + bj;
        float* zr = g_Zx + (size_t)col * MROWS + M0 + ty * 8;
        *reinterpret_cast<float4*>(zr)     = lo;
        *reinterpret_cast<float4*>(zr + 4) = hi;
    }
}

// ============================================================================
// Kernel 2: persistent recurrence, 128 CTAs x 256 threads.
// warp kq (0..7) owns k-range [kq*32, kq*32+32); lane: cg=gate (0..3),
// bg=batch-quad (0..7); thread computes cols {2cg,2cg+1} x 4 batches.
// Grid sync: R2-proven counter barrier (red.release + tid0 ld.acquire poll).
// ============================================================================
#define WPAD 260
#define PPAD 36

__global__ __launch_bounds__(REC_THREADS, 1)
void lstm_rec(const float* __restrict__ Wf, const float* __restrict__ Wi,
              const float* __restrict__ Wo, const float* __restrict__ Wc,
              float* __restrict__ out)
{
    extern __shared__ float smem[];
    float* s_Wh   = smem;                   // [8][WPAD]  c = 2*gate + u
    float* s_h    = s_Wh + 8 * WPAD;        // [256][32]  [k][b]
    float* s_part = s_h + 256 * 32;         // [64][PPAD] [(kq*8+c)][b]
    float* s_gate = s_part + 64 * PPAD;     // [4][65]
    float* s_c    = s_gate + 4 * 65;        // [64]

    const int tid = threadIdx.x;
    const int c0  = blockIdx.x * UNITS_PER_CTA;
    const float* Wg[4] = {Wf, Wi, Wo, Wc};

    // stage Wh slice once: s_Wh[c][k] = Wg[c/2][(256+k)*256 + c0 + (c&1)]
    for (int idx = tid; idx < 8 * 256; idx += REC_THREADS) {
        int cc = idx >> 8;
        int k  = idx & 255;
        s_Wh[cc * WPAD + k] = Wg[cc >> 1][(size_t)(256 + k) * 256 + c0 + (cc & 1)];
    }
    if (tid < 64) s_c[tid] = 0.f;
    if (tid < UNITS_PER_CTA * BATCH) {
        int u = tid >> 5, b = tid & 31;
        g_h[0][(c0 + u) * 32 + b] = 0.f;
    }

    const int kq   = tid >> 5;              // warp id = k-range
    const int lane = tid & 31;
    const int cg   = lane >> 3;             // gate 0..3
    const int bg   = lane & 7;              // batch quad

    const float* wrow0 = s_Wh + (2 * cg) * WPAD + kq * 32;
    const float* wrow1 = wrow0 + WPAD;
    const float* hbase = s_h + (kq * 32) * 32 + 4 * bg;
    float* pr0 = s_part + (kq * 8 + 2 * cg + 0) * PPAD + 4 * bg;
    float* pr1 = pr0 + PPAD;

    // Zx columns for this thread (warp 0 only consumes them)
    const size_t zc0 = (size_t)(cg * 256 + c0) * MROWS;       // u=0 column
    const size_t zc1 = zc0 + MROWS;                           // u=1 column

    // prefetch Zx(0): gemm_zx completed before this kernel starts
    float4 p0 = make_float4(0.f, 0.f, 0.f, 0.f), p1 = p0;
    if (kq == 0) {
        p0 = __ldcg(reinterpret_cast<const float4*>(g_Zx + zc0 + 4 * bg));
        p1 = __ldcg(reinterpret_cast<const float4*>(g_Zx + zc1 + 4 * bg));
    }

    // initial grid sync (round 1): weights staged + h0 zeroed everywhere
    __syncthreads();
    if (tid == 0) {
        asm volatile("red.release.gpu.global.add.s32 [%0], %1;"
                     :: "l"(&g_bar_count), "r"(1) : "memory");
        int v;
        do {
            asm volatile("ld.acquire.gpu.global.b32 %0, [%1];"
                         : "=r"(v) : "l"(&g_bar_count) : "memory");
        } while (v < NCTA);
    }
    __syncthreads();

    for (int t = 0; t < T_STEPS; t++) {
        // each warp stages its own 1KB h-slice (rows kq*32..kq*32+31)
        {
            const float4* src = reinterpret_cast<const float4*>(g_h[t & 1] + kq * 1024);
            float4* dst = reinterpret_cast<float4*>(s_h + kq * 1024);
            float4 r[8];
            #pragma unroll
            for (int i = 0; i < 8; i++) r[i] = __ldcg(src + lane + 32 * i);
            #pragma unroll
            for (int i = 0; i < 8; i++) dst[lane + 32 * i] = r[i];
            __syncwarp();
        }

        // acc init: warp 0 carries Zx, others 0
        float4 A0, A1;
        if (kq == 0) { A0 = p0; A1 = p1; }
        else { A0 = make_float4(0.f,0.f,0.f,0.f); A1 = A0; }

        // prefetch Zx(t+1) (off critical path, overlaps FMA below)
        if (kq == 0 && t + 1 < T_STEPS) {
            const float* zb = g_Zx + (size_t)(t + 1) * 32 + 4 * bg;
            p0 = __ldcg(reinterpret_cast<const float4*>(zb + zc0));
            p1 = __ldcg(reinterpret_cast<const float4*>(zb + zc1));
        }

        // dot over 32 k's: 2 cols x 4 batches per thread
        #pragma unroll
        for (int k4 = 0; k4 < 8; k4++) {
            float4 w0 = *reinterpret_cast<const float4*>(wrow0 + k4 * 4);
            float4 w1 = *reinterpret_cast<const float4*>(wrow1 + k4 * 4);
            const float* hb = hbase + (k4 * 4) * 32;
            float4 h;
            h = *reinterpret_cast<const float4*>(hb);
            A0.x = fmaf(w0.x, h.x, A0.x); A0.y = fmaf(w0.x, h.y, A0.y);
            A0.z = fmaf(w0.x, h.z, A0.z); A0.w = fmaf(w0.x, h.w, A0.w);
            A1.x = fmaf(w1.x, h.x, A1.x); A1.y = fmaf(w1.x, h.y, A1.y);
            A1.z = fmaf(w1.x, h.z, A1.z); A1.w = fmaf(w1.x, h.w, A1.w);
            h = *reinterpret_cast<const float4*>(hb + 32);
            A0.x = fmaf(w0.y, h.x, A0.x); A0.y = fmaf(w0.y, h.y, A0.y);
            A0.z = fmaf(w0.y, h.z, A0.z); A0.w = fmaf(w0.y, h.w, A0.w);
            A1.x = fmaf(w1.y, h.x, A1.x); A1.y = fmaf(w1.y, h.y, A1.y);
            A1.z = fmaf(w1.y, h.z, A1.z); A1.w = fmaf(w1.y, h.w, A1.w);
            h = *reinterpret_cast<const float4*>(hb + 64);
            A0.x = fmaf(w0.z, h.x, A0.x); A0.y = fmaf(w0.z, h.y, A0.y);
            A0.z = fmaf(w0.z, h.z, A0.z); A0.w = fmaf(w0.z, h.w, A0.w);
            A1.x = fmaf(w1.z, h.x, A1.x); A1.y = fmaf(w1.z, h.y, A1.y);
            A1.z = fmaf(w1.z, h.z, A1.z); A1.w = fmaf(w1.z, h.w, A1.w);
            h = *reinterpret_cast<const float4*>(hb + 96);
            A0.x = fmaf(w0.w, h.x, A0.x); A0.y = fmaf(w0.w, h.y, A0.y);
            A0.z = fmaf(w0.w, h.z, A0.z); A0.w = fmaf(w0.w, h.w, A0.w);
            A1.x = fmaf(w1.w, h.x, A1.x); A1.y = fmaf(w1.w, h.y, A1.y);
            A1.z = fmaf(w1.w, h.z, A1.z); A1.w = fmaf(w1.w, h.w, A1.w);
        }
        *reinterpret_cast<float4*>(pr0) = A0;
        *reinterpret_cast<float4*>(pr1) = A1;
        __syncthreads();                    // s_part complete

        // stage A: all 256 threads, one (gate, u, b) each
        {
            int ga = tid >> 6;
            int uu = (tid >> 5) & 1;
            int bb = tid & 31;
            float s = 0.f;
            #pragma unroll
            for (int q = 0; q < 8; q++)
                s += s_part[(q * 8 + 2 * ga + uu) * PPAD + bb];
            float val = (ga < 3) ? (1.f / (1.f + __expf(-s))) : tanhf(s);
            s_gate[ga * 65 + uu * 32 + bb] = val;
        }
        __syncthreads();                    // s_gate complete

        // stage B: 64 threads (u, b) update c, publish h
        if (tid < 64) {
            float fg = s_gate[tid];
            float ig = s_gate[65 + tid];
            float og = s_gate[130 + tid];
            float gg = s_gate[195 + tid];
            float cv = fmaf(fg, s_c[tid], ig * gg);
            s_c[tid] = cv;
            float hv = og * tanhf(cv);
            int u = tid >> 5, bb = tid & 31;
            g_h[(t + 1) & 1][(c0 + u) * 32 + bb] = hv;
            out[((size_t)bb * T_STEPS + (T_STEPS - 1 - t)) * HID + c0 + u] = hv;
            asm volatile("bar.sync 1, 64;" ::: "memory");   // warps 0-1 done
            if (tid == 0) {
                asm volatile("red.release.gpu.global.add.s32 [%0], %1;"
                             :: "l"(&g_bar_count), "r"(1) : "memory");
            }
        }
        // grid sync: tid0 polls, everyone waits at syncthreads
        if (t + 1 < T_STEPS) {
            if (tid == 0) {
                const int target = (t + 2) * NCTA;
                int v;
                do {
                    asm volatile("ld.acquire.gpu.global.b32 %0, [%1];"
                                 : "=r"(v) : "l"(&g_bar_count) : "memory");
                } while (v < target);
            }
            __syncthreads();
        }
    }
}

// ============================================================================
extern "C" void kernel_launch(void* const* d_in, const int* in_sizes, int n_in,
                              void* d_out, int out_size)
{
    const float* x  = (const float*)d_in[0];
    const float* Wf = (const float*)d_in[1];
    const float* bf = (const float*)d_in[2];
    const float* Wi = (const float*)d_in[3];
    const float* bi = (const float*)d_in[4];
    const float* Wo = (const float*)d_in[5];
    const float* bo = (const float*)d_in[6];
    const float* Wc = (const float*)d_in[7];
    const float* bc = (const float*)d_in[8];
    float* out = (float*)d_out;

    const int smem_rec = (8 * WPAD + 256 * 32 + 64 * PPAD + 4 * 65 + 64) * sizeof(float);
    cudaFuncSetAttribute(lstm_rec, cudaFuncAttributeMaxDynamicSharedMemorySize, smem_rec);

    dim3 g1(ZCOLS / 128, MROWS / 128);   // 8 x 512
    gemm_zx<<<g1, 256>>>(x, Wf, bf, Wi, bi, Wo, bo, Wc, bc);
    lstm_rec<<<NCTA, REC_THREADS, smem_rec>>>(Wf, Wi, Wo, Wc, out);
}